// round 12
// baseline (speedup 1.0000x reference)
#include <cuda_runtime.h>
#include <cuda_bf16.h>

// Problem constants (fixed by setup_inputs):
//   x: [B=2, C=3, D=128, H=160, W=160] float32, num_steps = 6
#define BB    2
#define DD    128
#define HH    160
#define WW    160
#define PLANE (DD * HH * WW)          // 3,276,800 voxels per (batch) volume
#define NVOX  (BB * PLANE)

// Interleaved ping-pong scratch: float4 per voxel = (flow_d, flow_h, flow_w, 0).
// Batches processed sequentially so the active set (~105 MB) mostly fits L2.
__device__ float4 g_bufA[NVOX];
__device__ float4 g_bufB[NVOX];

__device__ __forceinline__ int clampi(int v, int lo, int hi) {
    return min(max(v, lo), hi);
}

// ---------------------------------------------------------------------------
// K1: fused steps 1+2+3 (one batch): planar x -> interleaved v3.
//   v0(y) = s*x(y); v1(y) = v0(y) + v0(q0(y));  v2(y) = v1(y) + v1(q1(y));
//   v3(p) = v2(p) + v2(q2(p)).
// All recomputation is bitwise-identical to the pass-by-pass formula.
// Gather radius <= ~3 voxels -> L1-local.
// ---------------------------------------------------------------------------
__global__ __launch_bounds__(256) void sq_fuse123(const float* __restrict__ xb,
                                                  float4* __restrict__ db,
                                                  float s) {
    const int W4 = WW / 4;
    int idx = blockIdx.x * blockDim.x + threadIdx.x;   // grid covers DD*HH*W4
    int w4 = idx % W4;
    int t  = idx / W4;
    int h  = t % HH;
    int d  = t / HH;

    const int p = (d * HH + h) * WW + w4 * 4;

    float4 f0 = *reinterpret_cast<const float4*>(xb + p);              // d-flow
    float4 f1 = *reinterpret_cast<const float4*>(xb + p + PLANE);      // h-flow
    float4 f2 = *reinterpret_cast<const float4*>(xb + p + 2 * PLANE);  // w-flow

    float v0d[4] = {s * f0.x, s * f0.y, s * f0.z, s * f0.w};
    float v0h[4] = {s * f1.x, s * f1.y, s * f1.z, s * f1.w};
    float v0w[4] = {s * f2.x, s * f2.y, s * f2.z, s * f2.w};

#pragma unroll
    for (int j = 0; j < 4; ++j) {
        const int w = w4 * 4 + j;

        // ---- v1(p) ----
        int a_d = clampi(__float2int_rn((float)d + v0d[j]), 0, DD - 1);
        int a_h = clampi(__float2int_rn((float)h + v0h[j]), 0, HH - 1);
        int a_w = clampi(__float2int_rn((float)w + v0w[j]), 0, WW - 1);
        int qa = (a_d * HH + a_h) * WW + a_w;                  // q0(p)
        float v1pd = v0d[j] + s * xb[qa];
        float v1ph = v0h[j] + s * xb[qa + PLANE];
        float v1pw = v0w[j] + s * xb[qa + 2 * PLANE];

        // ---- v2(p) = v1(p) + v1(q1) ----
        int b_d = clampi(__float2int_rn((float)d + v1pd), 0, DD - 1);
        int b_h = clampi(__float2int_rn((float)h + v1ph), 0, HH - 1);
        int b_w = clampi(__float2int_rn((float)w + v1pw), 0, WW - 1);
        int qb = (b_d * HH + b_h) * WW + b_w;                  // q1(p)
        float u0d = s * xb[qb];
        float u0h = s * xb[qb + PLANE];
        float u0w = s * xb[qb + 2 * PLANE];
        int c_d = clampi(__float2int_rn((float)b_d + u0d), 0, DD - 1);
        int c_h = clampi(__float2int_rn((float)b_h + u0h), 0, HH - 1);
        int c_w = clampi(__float2int_rn((float)b_w + u0w), 0, WW - 1);
        int qc = (c_d * HH + c_h) * WW + c_w;                  // q0(q1)
        float v1bd = u0d + s * xb[qc];
        float v1bh = u0h + s * xb[qc + PLANE];
        float v1bw = u0w + s * xb[qc + 2 * PLANE];
        float v2pd = v1pd + v1bd;
        float v2ph = v1ph + v1bh;
        float v2pw = v1pw + v1bw;

        // ---- q2 = clamp(rn(p + v2(p))) ----
        int e_d = clampi(__float2int_rn((float)d + v2pd), 0, DD - 1);
        int e_h = clampi(__float2int_rn((float)h + v2ph), 0, HH - 1);
        int e_w = clampi(__float2int_rn((float)w + v2pw), 0, WW - 1);
        int qe = (e_d * HH + e_h) * WW + e_w;                  // q2(p)

        // ---- v2(q2) = v1(q2) + v1(q1(q2)) ----
        // v1(q2):
        float m0d = s * xb[qe];
        float m0h = s * xb[qe + PLANE];
        float m0w = s * xb[qe + 2 * PLANE];
        int f_d = clampi(__float2int_rn((float)e_d + m0d), 0, DD - 1);
        int f_h = clampi(__float2int_rn((float)e_h + m0h), 0, HH - 1);
        int f_w = clampi(__float2int_rn((float)e_w + m0w), 0, WW - 1);
        int qf = (f_d * HH + f_h) * WW + f_w;                  // q0(q2)
        float v1ed = m0d + s * xb[qf];
        float v1eh = m0h + s * xb[qf + PLANE];
        float v1ew = m0w + s * xb[qf + 2 * PLANE];
        // q1(q2):
        int g_d = clampi(__float2int_rn((float)e_d + v1ed), 0, DD - 1);
        int g_h = clampi(__float2int_rn((float)e_h + v1eh), 0, HH - 1);
        int g_w = clampi(__float2int_rn((float)e_w + v1ew), 0, WW - 1);
        int qg = (g_d * HH + g_h) * WW + g_w;
        // v1(q1(q2)):
        float n0d = s * xb[qg];
        float n0h = s * xb[qg + PLANE];
        float n0w = s * xb[qg + 2 * PLANE];
        int o_d = clampi(__float2int_rn((float)g_d + n0d), 0, DD - 1);
        int o_h = clampi(__float2int_rn((float)g_h + n0h), 0, HH - 1);
        int o_w = clampi(__float2int_rn((float)g_w + n0w), 0, WW - 1);
        int qo = (o_d * HH + o_h) * WW + o_w;                  // q0(q1(q2))
        float v1gd = n0d + s * xb[qo];
        float v1gh = n0h + s * xb[qo + PLANE];
        float v1gw = n0w + s * xb[qo + 2 * PLANE];

        float v2ed = v1ed + v1gd;
        float v2eh = v1eh + v1gh;
        float v2ew = v1ew + v1gw;

        // ---- v3(p) = v2(p) + v2(q2) ----
        db[p + j] = make_float4(v2pd + v2ed, v2ph + v2eh, v2pw + v2ew, 0.0f);
    }
}

// ---------------------------------------------------------------------------
// K2: fused steps 4+5 (one batch): interleaved v3 -> interleaved v5.
//   v4(y) = v3(y) + v3(q3(y));  v5(p) = v4(p) + v4(q4(p)),
//   with v4(q4) = v3(q4) + v3(q3(q4)) recomputed.
// 2 voxels/thread, warp-contiguous (2 independent dependent-chains in flight).
// PLANE = 6400 blocks * 512 voxels exactly.
// ---------------------------------------------------------------------------
__global__ __launch_bounds__(256) void sq_fuse45(const float4* __restrict__ src,
                                                 float4* __restrict__ dst) {
    const int lane = threadIdx.x & 31;
    const int warp = threadIdx.x >> 5;
    const int vA = blockIdx.x * 512 + warp * 64 + lane;   // in [0, PLANE)

#pragma unroll
    for (int k = 0; k < 2; ++k) {
        const int v = vA + k * 32;
        int w = v % WW;  int t = v / WW;
        int h = t % HH;  int d = t / HH;

        float4 a = src[v];                                  // v3(p)

        int id = clampi(__float2int_rn((float)d + a.x), 0, DD - 1);
        int ih = clampi(__float2int_rn((float)h + a.y), 0, HH - 1);
        int iw = clampi(__float2int_rn((float)w + a.z), 0, WW - 1);
        float4 g1 = src[(id * HH + ih) * WW + iw];          // v3(q3)

        float v4pd = a.x + g1.x;                            // v4(p)
        float v4ph = a.y + g1.y;
        float v4pw = a.z + g1.z;

        int jd = clampi(__float2int_rn((float)d + v4pd), 0, DD - 1);
        int jh = clampi(__float2int_rn((float)h + v4ph), 0, HH - 1);
        int jw = clampi(__float2int_rn((float)w + v4pw), 0, WW - 1);
        float4 b = src[(jd * HH + jh) * WW + jw];           // v3(q4)

        int kd = clampi(__float2int_rn((float)jd + b.x), 0, DD - 1);
        int kh = clampi(__float2int_rn((float)jh + b.y), 0, HH - 1);
        int kw = clampi(__float2int_rn((float)jw + b.z), 0, WW - 1);
        float4 g2 = src[(kd * HH + kh) * WW + kw];          // v3(q3(q4))

        float v4qd = b.x + g2.x;                            // v4(q4)
        float v4qh = b.y + g2.y;
        float v4qw = b.z + g2.z;

        dst[v] = make_float4(v4pd + v4qd, v4ph + v4qh, v4pw + v4qw, 0.0f);
    }
}

// ---------------------------------------------------------------------------
// K3: step 6 (one batch): interleaved v5 -> planar out. 4 voxels/thread,
// coalesced planar float4 stores per channel.
// ---------------------------------------------------------------------------
__global__ __launch_bounds__(256) void sq_last(const float4* __restrict__ sb,
                                               float* __restrict__ ob) {
    const int W4 = WW / 4;
    int idx = blockIdx.x * blockDim.x + threadIdx.x;
    int w4 = idx % W4;
    int t  = idx / W4;
    int h  = t % HH;
    int d  = t / HH;

    const int p = (d * HH + h) * WW + w4 * 4;

    float o0[4], o1[4], o2[4];
#pragma unroll
    for (int j = 0; j < 4; ++j) {
        float4 a = sb[p + j];
        int id = clampi(__float2int_rn((float)d + a.x), 0, DD - 1);
        int ih = clampi(__float2int_rn((float)h + a.y), 0, HH - 1);
        int iw = clampi(__float2int_rn((float)(w4 * 4 + j) + a.z), 0, WW - 1);
        float4 g = sb[(id * HH + ih) * WW + iw];
        o0[j] = a.x + g.x;
        o1[j] = a.y + g.y;
        o2[j] = a.z + g.z;
    }

    *reinterpret_cast<float4*>(ob + p)             = make_float4(o0[0], o0[1], o0[2], o0[3]);
    *reinterpret_cast<float4*>(ob + p + PLANE)     = make_float4(o1[0], o1[1], o1[2], o1[3]);
    *reinterpret_cast<float4*>(ob + p + 2 * PLANE) = make_float4(o2[0], o2[1], o2[2], o2[3]);
}

extern "C" void kernel_launch(void* const* d_in, const int* in_sizes, int n_in,
                              void* d_out, int out_size) {
    const float* x   = (const float*)d_in[0];
    float*       out = (float*)d_out;

    float4 *A = nullptr, *B = nullptr;
    cudaGetSymbolAddress((void**)&A, g_bufA);
    cudaGetSymbolAddress((void**)&B, g_bufB);

    const int tpb  = 256;
    const int blkQ = (DD * HH * (WW / 4)) / tpb;   // 3200 blocks (4 voxels/thread)
    const int blkM = PLANE / 512;                  // 6400 blocks (2 voxels/thread)

    const float s0 = 1.0f / 64.0f;                 // 1 / 2^num_steps (num_steps = 6)

    // Batch-sequential: keeps the per-batch working set mostly L2-resident.
    for (int b = 0; b < BB; ++b) {
        const float* xb = x   + (size_t)b * 3 * PLANE;
        float*       ob = out + (size_t)b * 3 * PLANE;
        float4*      Ab = A   + (size_t)b * PLANE;
        float4*      Bb = B   + (size_t)b * PLANE;

        sq_fuse123<<<blkQ, tpb>>>(xb, Ab, s0);  // steps 1+2+3: x -> v3
        sq_fuse45 <<<blkM, tpb>>>(Ab, Bb);      // steps 4+5:   v3 -> v5
        sq_last   <<<blkQ, tpb>>>(Bb, ob);      // step 6:      v5 -> out
    }
}

// round 13
// speedup vs baseline: 1.1595x; 1.1595x over previous
#include <cuda_runtime.h>
#include <cuda_bf16.h>

// Problem constants (fixed by setup_inputs):
//   x: [B=2, C=3, D=128, H=160, W=160] float32, num_steps = 6
#define BB    2
#define DD    128
#define HH    160
#define WW    160
#define PLANE (DD * HH * WW)          // 3,276,800 voxels per (batch) volume
#define NVOX  (BB * PLANE)

// Interleaved ping-pong scratch: float4 per voxel = (flow_d, flow_h, flow_w, 0).
// Batches processed sequentially so the active set (~105 MB) mostly fits L2.
__device__ float4 g_bufA[NVOX];
__device__ float4 g_bufB[NVOX];

__device__ __forceinline__ int clampi(int v, int lo, int hi) {
    return min(max(v, lo), hi);
}

// ---------------------------------------------------------------------------
// K1: fused steps 1+2 (one batch): planar x -> interleaved v2.
//   v0(y) = s*x(y); v1(y) = v0(y) + v0(q0(y)); v2(p) = v1(p) + v1(q1(p)).
// 2-deep recompute (5 scalar-gather sites/voxel) — measured ~24 us.
// ---------------------------------------------------------------------------
__global__ __launch_bounds__(256) void sq_fuse12(const float* __restrict__ xb,
                                                 float4* __restrict__ db,
                                                 float s) {
    const int W4 = WW / 4;
    int idx = blockIdx.x * blockDim.x + threadIdx.x;   // grid covers DD*HH*W4
    int w4 = idx % W4;
    int t  = idx / W4;
    int h  = t % HH;
    int d  = t / HH;

    const int p = (d * HH + h) * WW + w4 * 4;

    float4 f0 = *reinterpret_cast<const float4*>(xb + p);              // d-flow
    float4 f1 = *reinterpret_cast<const float4*>(xb + p + PLANE);      // h-flow
    float4 f2 = *reinterpret_cast<const float4*>(xb + p + 2 * PLANE);  // w-flow

    float v0d[4] = {s * f0.x, s * f0.y, s * f0.z, s * f0.w};
    float v0h[4] = {s * f1.x, s * f1.y, s * f1.z, s * f1.w};
    float v0w[4] = {s * f2.x, s * f2.y, s * f2.z, s * f2.w};

#pragma unroll
    for (int j = 0; j < 4; ++j) {
        const int w = w4 * 4 + j;

        // ---- v1(p) ----
        int a_d = clampi(__float2int_rn((float)d + v0d[j]), 0, DD - 1);
        int a_h = clampi(__float2int_rn((float)h + v0h[j]), 0, HH - 1);
        int a_w = clampi(__float2int_rn((float)w + v0w[j]), 0, WW - 1);
        int qa = (a_d * HH + a_h) * WW + a_w;                 // q0(p)
        float v1pd = v0d[j] + s * xb[qa];
        float v1ph = v0h[j] + s * xb[qa + PLANE];
        float v1pw = v0w[j] + s * xb[qa + 2 * PLANE];

        // ---- q1 = clamp(rn(p + v1(p))) ----
        int b_d = clampi(__float2int_rn((float)d + v1pd), 0, DD - 1);
        int b_h = clampi(__float2int_rn((float)h + v1ph), 0, HH - 1);
        int b_w = clampi(__float2int_rn((float)w + v1pw), 0, WW - 1);
        int qb = (b_d * HH + b_h) * WW + b_w;                 // q1

        // ---- v1(q1) recomputed ----
        float u0d = s * xb[qb];
        float u0h = s * xb[qb + PLANE];
        float u0w = s * xb[qb + 2 * PLANE];
        int c_d = clampi(__float2int_rn((float)b_d + u0d), 0, DD - 1);
        int c_h = clampi(__float2int_rn((float)b_h + u0h), 0, HH - 1);
        int c_w = clampi(__float2int_rn((float)b_w + u0w), 0, WW - 1);
        int qc = (c_d * HH + c_h) * WW + c_w;                 // q0(q1)
        float v1qd = u0d + s * xb[qc];
        float v1qh = u0h + s * xb[qc + PLANE];
        float v1qw = u0w + s * xb[qc + 2 * PLANE];

        // ---- v2(p) = v1(p) + v1(q1) ----
        db[p + j] = make_float4(v1pd + v1qd, v1ph + v1qh, v1pw + v1qw, 0.0f);
    }
}

// ---------------------------------------------------------------------------
// K2: fused steps 3+4 (one batch): interleaved v2 -> interleaved v4.
//   v3(y) = v2(y) + v2(q2(y));  v4(p) = v3(p) + v3(q3(p)),
//   with v3(q3) = v2(q3) + v2(q2(q3)) recomputed.
// 2 voxels/thread, warp-contiguous. PLANE = 6400 blocks * 512 voxels.
// ---------------------------------------------------------------------------
__global__ __launch_bounds__(256) void sq_fuse34(const float4* __restrict__ src,
                                                 float4* __restrict__ dst) {
    const int lane = threadIdx.x & 31;
    const int warp = threadIdx.x >> 5;
    const int vA = blockIdx.x * 512 + warp * 64 + lane;   // in [0, PLANE)

#pragma unroll
    for (int k = 0; k < 2; ++k) {
        const int v = vA + k * 32;
        int w = v % WW;  int t = v / WW;
        int h = t % HH;  int d = t / HH;

        float4 a = src[v];                                  // v2(p)

        int id = clampi(__float2int_rn((float)d + a.x), 0, DD - 1);
        int ih = clampi(__float2int_rn((float)h + a.y), 0, HH - 1);
        int iw = clampi(__float2int_rn((float)w + a.z), 0, WW - 1);
        float4 g1 = src[(id * HH + ih) * WW + iw];          // v2(q2)

        float v3pd = a.x + g1.x;                            // v3(p)
        float v3ph = a.y + g1.y;
        float v3pw = a.z + g1.z;

        int jd = clampi(__float2int_rn((float)d + v3pd), 0, DD - 1);
        int jh = clampi(__float2int_rn((float)h + v3ph), 0, HH - 1);
        int jw = clampi(__float2int_rn((float)w + v3pw), 0, WW - 1);
        float4 b = src[(jd * HH + jh) * WW + jw];           // v2(q3)

        int kd = clampi(__float2int_rn((float)jd + b.x), 0, DD - 1);
        int kh = clampi(__float2int_rn((float)jh + b.y), 0, HH - 1);
        int kw = clampi(__float2int_rn((float)jw + b.z), 0, WW - 1);
        float4 g2 = src[(kd * HH + kh) * WW + kw];          // v2(q2(q3))

        float v3qd = b.x + g2.x;                            // v3(q3)
        float v3qh = b.y + g2.y;
        float v3qw = b.z + g2.z;

        dst[v] = make_float4(v3pd + v3qd, v3ph + v3qh, v3pw + v3qw, 0.0f);
    }
}

// ---------------------------------------------------------------------------
// K3: fused steps 5+6 (one batch): interleaved v4 -> planar out v6.
//   v5(y) = v4(y) + v4(q4(y));  v6(p) = v5(p) + v5(q5(p)),
//   with v5(q5) = v4(q5) + v4(q4(q5)) recomputed.
// 4 consecutive-W voxels/thread for coalesced planar per-channel stores.
// ---------------------------------------------------------------------------
__global__ __launch_bounds__(256) void sq_fuse56last(const float4* __restrict__ sb,
                                                     float* __restrict__ ob) {
    const int W4 = WW / 4;
    int idx = blockIdx.x * blockDim.x + threadIdx.x;
    int w4 = idx % W4;
    int t  = idx / W4;
    int h  = t % HH;
    int d  = t / HH;

    const int p = (d * HH + h) * WW + w4 * 4;

    float o0[4], o1[4], o2[4];
#pragma unroll
    for (int j = 0; j < 4; ++j) {
        const int w = w4 * 4 + j;
        float4 a = sb[p + j];                               // v4(p)

        int id = clampi(__float2int_rn((float)d + a.x), 0, DD - 1);
        int ih = clampi(__float2int_rn((float)h + a.y), 0, HH - 1);
        int iw = clampi(__float2int_rn((float)w + a.z), 0, WW - 1);
        float4 g1 = sb[(id * HH + ih) * WW + iw];           // v4(q4)

        float v5pd = a.x + g1.x;                            // v5(p)
        float v5ph = a.y + g1.y;
        float v5pw = a.z + g1.z;

        int jd = clampi(__float2int_rn((float)d + v5pd), 0, DD - 1);
        int jh = clampi(__float2int_rn((float)h + v5ph), 0, HH - 1);
        int jw = clampi(__float2int_rn((float)w + v5pw), 0, WW - 1);
        float4 b = sb[(jd * HH + jh) * WW + jw];            // v4(q5)

        int kd = clampi(__float2int_rn((float)jd + b.x), 0, DD - 1);
        int kh = clampi(__float2int_rn((float)jh + b.y), 0, HH - 1);
        int kw = clampi(__float2int_rn((float)jw + b.z), 0, WW - 1);
        float4 g2 = sb[(kd * HH + kh) * WW + kw];           // v4(q4(q5))

        float v5qd = b.x + g2.x;                            // v5(q5)
        float v5qh = b.y + g2.y;
        float v5qw = b.z + g2.z;

        o0[j] = v5pd + v5qd;                                // v6(p)
        o1[j] = v5ph + v5qh;
        o2[j] = v5pw + v5qw;
    }

    *reinterpret_cast<float4*>(ob + p)             = make_float4(o0[0], o0[1], o0[2], o0[3]);
    *reinterpret_cast<float4*>(ob + p + PLANE)     = make_float4(o1[0], o1[1], o1[2], o1[3]);
    *reinterpret_cast<float4*>(ob + p + 2 * PLANE) = make_float4(o2[0], o2[1], o2[2], o2[3]);
}

extern "C" void kernel_launch(void* const* d_in, const int* in_sizes, int n_in,
                              void* d_out, int out_size) {
    const float* x   = (const float*)d_in[0];
    float*       out = (float*)d_out;

    float4 *A = nullptr, *B = nullptr;
    cudaGetSymbolAddress((void**)&A, g_bufA);
    cudaGetSymbolAddress((void**)&B, g_bufB);

    const int tpb  = 256;
    const int blkQ = (DD * HH * (WW / 4)) / tpb;   // 3200 blocks (4 voxels/thread)
    const int blkM = PLANE / 512;                  // 6400 blocks (2 voxels/thread)

    const float s0 = 1.0f / 64.0f;                 // 1 / 2^num_steps (num_steps = 6)

    // Batch-sequential: keeps the per-batch working set mostly L2-resident.
    for (int b = 0; b < BB; ++b) {
        const float* xb = x   + (size_t)b * 3 * PLANE;
        float*       ob = out + (size_t)b * 3 * PLANE;
        float4*      Ab = A   + (size_t)b * PLANE;
        float4*      Bb = B   + (size_t)b * PLANE;

        sq_fuse12    <<<blkQ, tpb>>>(xb, Ab, s0);  // steps 1+2: x  -> v2
        sq_fuse34    <<<blkM, tpb>>>(Ab, Bb);      // steps 3+4: v2 -> v4
        sq_fuse56last<<<blkQ, tpb>>>(Bb, ob);      // steps 5+6: v4 -> out
    }
}